// round 2
// baseline (speedup 1.0000x reference)
#include <cuda_runtime.h>
#include <cuda_bf16.h>

// Scratch: [b*3 + {0:inter, 1:psum, 2:tsum}]. Zero-initialized at module load;
// the finalizing block resets it to zero after every kernel run, so every
// graph replay sees identical initial state (deterministic).
__device__ double g_acc[24];
__device__ unsigned int g_done_count;

template <int BLOCK>
__global__ void dice_fused_kernel(const float4* __restrict__ pred,
                                  const float4* __restrict__ tgt,
                                  const float*  __restrict__ weight,
                                  float*        __restrict__ out,
                                  int n4_per_sample,
                                  int blocks_per_sample,
                                  int B) {
    const int b   = blockIdx.x / blocks_per_sample;
    const int blk = blockIdx.x % blocks_per_sample;

    const float4* __restrict__ p4 = pred + (size_t)b * n4_per_sample;
    const float4* __restrict__ t4 = tgt  + (size_t)b * n4_per_sample;

    float s_pt = 0.f, s_p = 0.f, s_t = 0.f;

    const int stride = blocks_per_sample * BLOCK;
    #pragma unroll 4
    for (int i = blk * BLOCK + threadIdx.x; i < n4_per_sample; i += stride) {
        float4 pv = __ldcs(&p4[i]);
        float4 tv = __ldcs(&t4[i]);

        float sp0 = 1.0f / (1.0f + __expf(-pv.x));
        float sp1 = 1.0f / (1.0f + __expf(-pv.y));
        float sp2 = 1.0f / (1.0f + __expf(-pv.z));
        float sp3 = 1.0f / (1.0f + __expf(-pv.w));

        s_p  += (sp0 + sp1) + (sp2 + sp3);
        s_t  += (tv.x + tv.y) + (tv.z + tv.w);
        s_pt += sp0 * tv.x + sp1 * tv.y + sp2 * tv.z + sp3 * tv.w;
    }

    // Warp reduce
    #pragma unroll
    for (int off = 16; off > 0; off >>= 1) {
        s_pt += __shfl_down_sync(0xffffffffu, s_pt, off);
        s_p  += __shfl_down_sync(0xffffffffu, s_p,  off);
        s_t  += __shfl_down_sync(0xffffffffu, s_t,  off);
    }

    __shared__ float sh_pt[BLOCK / 32];
    __shared__ float sh_p [BLOCK / 32];
    __shared__ float sh_t [BLOCK / 32];
    __shared__ bool  sh_is_last;

    const int lane = threadIdx.x & 31;
    const int wid  = threadIdx.x >> 5;
    if (lane == 0) { sh_pt[wid] = s_pt; sh_p[wid] = s_p; sh_t[wid] = s_t; }
    __syncthreads();

    if (wid == 0) {
        constexpr int NW = BLOCK / 32;
        float v_pt = (lane < NW) ? sh_pt[lane] : 0.f;
        float v_p  = (lane < NW) ? sh_p [lane] : 0.f;
        float v_t  = (lane < NW) ? sh_t [lane] : 0.f;
        #pragma unroll
        for (int off = NW / 2; off > 0; off >>= 1) {
            v_pt += __shfl_down_sync(0xffffffffu, v_pt, off);
            v_p  += __shfl_down_sync(0xffffffffu, v_p,  off);
            v_t  += __shfl_down_sync(0xffffffffu, v_t,  off);
        }
        if (lane == 0) {
            atomicAdd(&g_acc[b * 3 + 0], (double)v_pt);
            atomicAdd(&g_acc[b * 3 + 1], (double)v_p);
            atomicAdd(&g_acc[b * 3 + 2], (double)v_t);
            __threadfence();
            unsigned int prev = atomicAdd(&g_done_count, 1u);
            sh_is_last = (prev == gridDim.x - 1);
        }
    }
    __syncthreads();

    // Last block to finish: finalize + reset scratch for next replay.
    if (sh_is_last && threadIdx.x == 0) {
        volatile double* acc = g_acc;   // bypass stale L1 lines
        double total = 0.0;
        const double smooth = 1.0;
        for (int s = 0; s < B; ++s) {
            double w     = (double)weight[s];
            double inter = acc[s * 3 + 0] * w;
            double psum  = acc[s * 3 + 1] * w;
            double tsum  = acc[s * 3 + 2] * w;
            double dice  = (2.0 * inter + smooth) / (psum + tsum + smooth);
            total += 1.0 - dice;
        }
        out[0] = (float)(total / (double)B);
        // Reset for the next graph replay.
        for (int s = 0; s < B * 3; ++s) acc[s] = 0.0;
        __threadfence();
        g_done_count = 0u;
    }
}

extern "C" void kernel_launch(void* const* d_in, const int* in_sizes, int n_in,
                              void* d_out, int out_size) {
    const float* pred   = (const float*)d_in[0];
    const float* target = (const float*)d_in[1];
    const float* weight = (const float*)d_in[2];
    float* out = (float*)d_out;

    const int B = in_sizes[2];               // 3
    const int n_per = in_sizes[0] / B;       // 192^3 = 7,077,888
    const int n4_per = n_per / 4;            // 1,769,472

    constexpr int BLOCK = 256;
    // 576 * 256 = 147456; 1,769,472 / 147,456 = 12 exact iterations/thread.
    const int blocks_per_sample = 576;

    dice_fused_kernel<BLOCK><<<B * blocks_per_sample, BLOCK>>>(
        (const float4*)pred, (const float4*)target, weight, out,
        n4_per, blocks_per_sample, B);
}

// round 3
// speedup vs baseline: 1.1754x; 1.1754x over previous
#include <cuda_runtime.h>
#include <cuda_bf16.h>

// Scratch: [b*3 + {0:inter, 1:psum, 2:tsum}]. Zero at module load; the
// finalizing block resets to zero after each run, so every graph replay sees
// identical initial state.
__device__ double g_acc[24];
__device__ unsigned int g_done_count;

__device__ __forceinline__ float fast_sigmoid(float x) {
    // sigmoid(x) = 0.5 * tanh(x/2) + 0.5  — single MUFU.TANH on sm_75+
    float t;
    asm("tanh.approx.f32 %0, %1;" : "=f"(t) : "f"(x * 0.5f));
    return fmaf(t, 0.5f, 0.5f);
}

template <int BLOCK>
__global__ void dice_fused_kernel(const float4* __restrict__ pred,
                                  const float4* __restrict__ tgt,
                                  const float*  __restrict__ weight,
                                  float*        __restrict__ out,
                                  int n4_per_sample,
                                  int blocks_per_sample,
                                  int B) {
    const int b   = blockIdx.x / blocks_per_sample;
    const int blk = blockIdx.x % blocks_per_sample;

    const float4* __restrict__ p4 = pred + (size_t)b * n4_per_sample;
    const float4* __restrict__ t4 = tgt  + (size_t)b * n4_per_sample;

    float s_pt = 0.f, s_p = 0.f, s_t = 0.f;

    const int stride = blocks_per_sample * BLOCK;
    int i = blk * BLOCK + threadIdx.x;

    // Main loop: 8 independent LDG.128 front-batched per trip (MLP ~8).
    for (; i + 3 * stride < n4_per_sample; i += 4 * stride) {
        float4 pv0 = __ldcs(&p4[i]);
        float4 pv1 = __ldcs(&p4[i +     stride]);
        float4 pv2 = __ldcs(&p4[i + 2 * stride]);
        float4 pv3 = __ldcs(&p4[i + 3 * stride]);
        float4 tv0 = __ldcs(&t4[i]);
        float4 tv1 = __ldcs(&t4[i +     stride]);
        float4 tv2 = __ldcs(&t4[i + 2 * stride]);
        float4 tv3 = __ldcs(&t4[i + 3 * stride]);

        #define ACC(pv, tv)                                                  \
        {                                                                    \
            float a = fast_sigmoid(pv.x);                                    \
            float c = fast_sigmoid(pv.y);                                    \
            float d = fast_sigmoid(pv.z);                                    \
            float e = fast_sigmoid(pv.w);                                    \
            s_p  += (a + c) + (d + e);                                       \
            s_t  += (tv.x + tv.y) + (tv.z + tv.w);                           \
            s_pt += a * tv.x + c * tv.y + d * tv.z + e * tv.w;               \
        }
        ACC(pv0, tv0) ACC(pv1, tv1) ACC(pv2, tv2) ACC(pv3, tv3)
    }
    // Tail (empty when sizes divide exactly, which they do here).
    for (; i < n4_per_sample; i += stride) {
        float4 pv = __ldcs(&p4[i]);
        float4 tv = __ldcs(&t4[i]);
        ACC(pv, tv)
    }
    #undef ACC

    // Warp reduce
    #pragma unroll
    for (int off = 16; off > 0; off >>= 1) {
        s_pt += __shfl_down_sync(0xffffffffu, s_pt, off);
        s_p  += __shfl_down_sync(0xffffffffu, s_p,  off);
        s_t  += __shfl_down_sync(0xffffffffu, s_t,  off);
    }

    __shared__ float sh_pt[BLOCK / 32];
    __shared__ float sh_p [BLOCK / 32];
    __shared__ float sh_t [BLOCK / 32];
    __shared__ bool  sh_is_last;

    const int lane = threadIdx.x & 31;
    const int wid  = threadIdx.x >> 5;
    if (lane == 0) { sh_pt[wid] = s_pt; sh_p[wid] = s_p; sh_t[wid] = s_t; }
    __syncthreads();

    if (wid == 0) {
        constexpr int NW = BLOCK / 32;
        float v_pt = (lane < NW) ? sh_pt[lane] : 0.f;
        float v_p  = (lane < NW) ? sh_p [lane] : 0.f;
        float v_t  = (lane < NW) ? sh_t [lane] : 0.f;
        #pragma unroll
        for (int off = NW / 2; off > 0; off >>= 1) {
            v_pt += __shfl_down_sync(0xffffffffu, v_pt, off);
            v_p  += __shfl_down_sync(0xffffffffu, v_p,  off);
            v_t  += __shfl_down_sync(0xffffffffu, v_t,  off);
        }
        if (lane == 0) {
            atomicAdd(&g_acc[b * 3 + 0], (double)v_pt);
            atomicAdd(&g_acc[b * 3 + 1], (double)v_p);
            atomicAdd(&g_acc[b * 3 + 2], (double)v_t);
            __threadfence();
            unsigned int prev = atomicAdd(&g_done_count, 1u);
            sh_is_last = (prev == gridDim.x - 1);
        }
    }
    __syncthreads();

    if (sh_is_last && threadIdx.x == 0) {
        volatile double* acc = g_acc;
        double total = 0.0;
        const double smooth = 1.0;
        for (int s = 0; s < B; ++s) {
            double w     = (double)weight[s];
            double inter = acc[s * 3 + 0] * w;
            double psum  = acc[s * 3 + 1] * w;
            double tsum  = acc[s * 3 + 2] * w;
            double dice  = (2.0 * inter + smooth) / (psum + tsum + smooth);
            total += 1.0 - dice;
        }
        out[0] = (float)(total / (double)B);
        for (int s = 0; s < B * 3; ++s) acc[s] = 0.0;
        __threadfence();
        g_done_count = 0u;
    }
}

extern "C" void kernel_launch(void* const* d_in, const int* in_sizes, int n_in,
                              void* d_out, int out_size) {
    const float* pred   = (const float*)d_in[0];
    const float* target = (const float*)d_in[1];
    const float* weight = (const float*)d_in[2];
    float* out = (float*)d_out;

    const int B = in_sizes[2];               // 3
    const int n_per = in_sizes[0] / B;       // 192^3 = 7,077,888
    const int n4_per = n_per / 4;            // 1,769,472

    constexpr int BLOCK = 256;
    // 576*256 = 147456 threads/sample; 1,769,472 / 147,456 = 12 exact trips
    // (3 trips of the 4x-batched loop, no tail).
    const int blocks_per_sample = 576;

    dice_fused_kernel<BLOCK><<<B * blocks_per_sample, BLOCK>>>(
        (const float4*)pred, (const float4*)target, weight, out,
        n4_per, blocks_per_sample, B);
}

// round 4
// speedup vs baseline: 1.1969x; 1.0183x over previous
#include <cuda_runtime.h>
#include <cuda_bf16.h>

// Scratch: [b*3 + {0:inter, 1:psum, 2:tsum}]. Zero at module load; the
// finalizing block resets to zero after each run, so every graph replay sees
// identical initial state.
__device__ double g_acc[24];
__device__ unsigned int g_done_count;

__device__ __forceinline__ float fast_sigmoid(float x) {
    // sigmoid(x) = 0.5 * tanh(x/2) + 0.5  — single MUFU.TANH on sm_75+
    float t;
    asm("tanh.approx.f32 %0, %1;" : "=f"(t) : "f"(x * 0.5f));
    return fmaf(t, 0.5f, 0.5f);
}

template <int BLOCK>
__global__ void __launch_bounds__(BLOCK, 4)
dice_fused_kernel(const float4* __restrict__ pred,
                  const float4* __restrict__ tgt,
                  const float*  __restrict__ weight,
                  float*        __restrict__ out,
                  int n4_per_sample,
                  int blocks_per_sample,
                  int B) {
    const int b   = blockIdx.x / blocks_per_sample;
    const int blk = blockIdx.x % blocks_per_sample;

    const float4* __restrict__ p4 = pred + (size_t)b * n4_per_sample;
    const float4* __restrict__ t4 = tgt  + (size_t)b * n4_per_sample;

    float s_pt = 0.f, s_p = 0.f, s_t = 0.f;

    const int stride = blocks_per_sample * BLOCK;
    int i = blk * BLOCK + threadIdx.x;

    // Main loop: 8 independent LDG.128 front-batched per trip. With the
    // 64-reg budget from __launch_bounds__(BLOCK,4), all 8 stay live.
    for (; i + 3 * stride < n4_per_sample; i += 4 * stride) {
        const float4* pp = p4 + i;
        const float4* tp = t4 + i;
        float4 pv0 = __ldcs(pp);
        float4 pv1 = __ldcs(pp +     stride);
        float4 pv2 = __ldcs(pp + 2 * stride);
        float4 pv3 = __ldcs(pp + 3 * stride);
        float4 tv0 = __ldcs(tp);
        float4 tv1 = __ldcs(tp +     stride);
        float4 tv2 = __ldcs(tp + 2 * stride);
        float4 tv3 = __ldcs(tp + 3 * stride);

        #define ACC(pv, tv)                                                  \
        {                                                                    \
            float a = fast_sigmoid(pv.x);                                    \
            float c = fast_sigmoid(pv.y);                                    \
            float d = fast_sigmoid(pv.z);                                    \
            float e = fast_sigmoid(pv.w);                                    \
            s_p  += (a + c) + (d + e);                                       \
            s_t  += (tv.x + tv.y) + (tv.z + tv.w);                           \
            s_pt += a * tv.x + c * tv.y + d * tv.z + e * tv.w;               \
        }
        ACC(pv0, tv0) ACC(pv1, tv1) ACC(pv2, tv2) ACC(pv3, tv3)
    }
    // Tail (empty for this shape).
    for (; i < n4_per_sample; i += stride) {
        float4 pv = __ldcs(&p4[i]);
        float4 tv = __ldcs(&t4[i]);
        ACC(pv, tv)
    }
    #undef ACC

    // Warp reduce
    #pragma unroll
    for (int off = 16; off > 0; off >>= 1) {
        s_pt += __shfl_down_sync(0xffffffffu, s_pt, off);
        s_p  += __shfl_down_sync(0xffffffffu, s_p,  off);
        s_t  += __shfl_down_sync(0xffffffffu, s_t,  off);
    }

    __shared__ float sh_pt[BLOCK / 32];
    __shared__ float sh_p [BLOCK / 32];
    __shared__ float sh_t [BLOCK / 32];
    __shared__ bool  sh_is_last;

    const int lane = threadIdx.x & 31;
    const int wid  = threadIdx.x >> 5;
    if (lane == 0) { sh_pt[wid] = s_pt; sh_p[wid] = s_p; sh_t[wid] = s_t; }
    __syncthreads();

    if (wid == 0) {
        constexpr int NW = BLOCK / 32;
        float v_pt = (lane < NW) ? sh_pt[lane] : 0.f;
        float v_p  = (lane < NW) ? sh_p [lane] : 0.f;
        float v_t  = (lane < NW) ? sh_t [lane] : 0.f;
        #pragma unroll
        for (int off = NW / 2; off > 0; off >>= 1) {
            v_pt += __shfl_down_sync(0xffffffffu, v_pt, off);
            v_p  += __shfl_down_sync(0xffffffffu, v_p,  off);
            v_t  += __shfl_down_sync(0xffffffffu, v_t,  off);
        }
        if (lane == 0) {
            atomicAdd(&g_acc[b * 3 + 0], (double)v_pt);
            atomicAdd(&g_acc[b * 3 + 1], (double)v_p);
            atomicAdd(&g_acc[b * 3 + 2], (double)v_t);
            __threadfence();
            unsigned int prev = atomicAdd(&g_done_count, 1u);
            sh_is_last = (prev == gridDim.x - 1);
        }
    }
    __syncthreads();

    if (sh_is_last && threadIdx.x == 0) {
        volatile double* acc = g_acc;
        double total = 0.0;
        const double smooth = 1.0;
        for (int s = 0; s < B; ++s) {
            double w     = (double)weight[s];
            double inter = acc[s * 3 + 0] * w;
            double psum  = acc[s * 3 + 1] * w;
            double tsum  = acc[s * 3 + 2] * w;
            double dice  = (2.0 * inter + smooth) / (psum + tsum + smooth);
            total += 1.0 - dice;
        }
        out[0] = (float)(total / (double)B);
        for (int s = 0; s < B * 3; ++s) acc[s] = 0.0;
        __threadfence();
        g_done_count = 0u;
    }
}

extern "C" void kernel_launch(void* const* d_in, const int* in_sizes, int n_in,
                              void* d_out, int out_size) {
    const float* pred   = (const float*)d_in[0];
    const float* target = (const float*)d_in[1];
    const float* weight = (const float*)d_in[2];
    float* out = (float*)d_out;

    const int B = in_sizes[2];               // 3
    const int n_per = in_sizes[0] / B;       // 192^3 = 7,077,888
    const int n4_per = n_per / 4;            // 1,769,472

    constexpr int BLOCK = 256;
    // 576*256 = 147456 threads/sample; 1,769,472 / 147,456 = 12 exact trips
    // (3 trips of the 4x-batched loop, no tail).
    const int blocks_per_sample = 576;

    dice_fused_kernel<BLOCK><<<B * blocks_per_sample, BLOCK>>>(
        (const float4*)pred, (const float4*)target, weight, out,
        n4_per, blocks_per_sample, B);
}